// round 15
// baseline (speedup 1.0000x reference)
#include <cuda_runtime.h>
#include <cuda_fp16.h>
#include <math.h>
#include <stdint.h>

#define HH 128
#define WW 128
#define HW 16384
#define NIMG 20
#define CHUNK 4

// ---------------- scratch: all activations channel-pair-interleaved u32 = half2(ci_even, ci_odd) ----------------
__device__ unsigned g_bufA[(size_t)NIMG * 32 * HW];
__device__ unsigned g_bufB[(size_t)NIMG * 32 * HW];
__device__ unsigned g_bufT[(size_t)NIMG * 32 * HW];
__device__ unsigned g_off [(size_t)NIMG * 32 * HW];
__device__ unsigned g_om  [(size_t)NIMG * 108 * HW];
__device__ unsigned g_wprep[663552];

// ---------------- helpers ----------------
__device__ __forceinline__ uint32_t smem_u32(const void* p) {
    uint32_t a;
    asm("{ .reg .u64 t; cvta.to.shared.u64 t, %1; cvt.u32.u64 %0, t; }" : "=r"(a) : "l"(p));
    return a;
}
__device__ __forceinline__ void cp16(uint32_t dst, const void* src, unsigned nbytes) {
    asm volatile("cp.async.cg.shared.global [%0], [%1], 16, %2;"
                 :: "r"(dst), "l"(src), "r"(nbytes) : "memory");
}
__device__ __forceinline__ void cp_commit() {
    asm volatile("cp.async.commit_group;" ::: "memory");
}
__device__ __forceinline__ void cp_wait1() {
    asm volatile("cp.async.wait_group 1;" ::: "memory");
}
__device__ __forceinline__ void cp_wait2() {
    asm volatile("cp.async.wait_group 2;" ::: "memory");
}
__device__ __forceinline__ void cp_wait0() {
    asm volatile("cp.async.wait_group 0;" ::: "memory");
}
__device__ __forceinline__ void mma_f16_k16(float* c, uint4 a, unsigned b0, unsigned b1) {
    asm volatile(
        "mma.sync.aligned.m16n8k16.row.col.f32.f16.f16.f32 "
        "{%0,%1,%2,%3}, {%4,%5,%6,%7}, {%8,%9}, {%0,%1,%2,%3};"
        : "+f"(c[0]), "+f"(c[1]), "+f"(c[2]), "+f"(c[3])
        : "r"(a.x), "r"(a.y), "r"(a.z), "r"(a.w), "r"(b0), "r"(b1));
}
__device__ __forceinline__ void mma_f16_k8(float* c, uint2 a, unsigned b0) {
    asm volatile(
        "mma.sync.aligned.m16n8k8.row.col.f32.f16.f16.f32 "
        "{%0,%1,%2,%3}, {%4,%5}, {%6}, {%0,%1,%2,%3};"
        : "+f"(c[0]), "+f"(c[1]), "+f"(c[2]), "+f"(c[3])
        : "r"(a.x), "r"(a.y), "r"(b0));
}
__device__ __forceinline__ unsigned pack_h2(float lo, float hi) {
    __half2 h = __floats2half2_rn(lo, hi);
    return *(unsigned*)&h;
}
__device__ __forceinline__ float h2_get(unsigned w, int sel) {
    __half2 h = *(__half2*)&w;
    return sel ? __half2float(__high2half(h)) : __half2float(__low2half(h));
}

// ---------------- single fused weight-prep kernel ----------------
__global__ void prep_all_kernel(const float* __restrict__ res_w1, const float* __restrict__ res_w2,
                                const float* __restrict__ w_bn,  const float* __restrict__ off_w,
                                const float* __restrict__ com_w, const float* __restrict__ dcn_w,
                                unsigned* __restrict__ dst)
{
    const int gid = blockIdx.x * 256 + threadIdx.x;   // 663552 = 2592 * 256
    const float* src;
    int local, Cin, Cout;
    bool isGemm = false;
    if (gid < 184320) {
        const int ci = gid / 18432; local = gid - ci * 18432;
        src = (ci < 5) ? res_w1 + (size_t)ci * 36864 : res_w2 + (size_t)(ci - 5) * 36864;
        Cin = 64; Cout = 64;
    } else if (gid < 221184) {
        local = gid - 184320; src = w_bn; Cin = 128; Cout = 64;
    } else if (gid < 294912) {
        const int t = gid - 221184; const int d = t / 18432; local = t - d * 18432;
        src = off_w + (size_t)d * 36864; Cin = 64; Cout = 64;
    } else if (gid < 589824) {
        const int t = gid - 294912; const int d = t / 73728; local = t - d * 73728;
        src = com_w + (size_t)d * 124416; Cin = 64; Cout = 216;
    } else {
        const int t = gid - 589824; const int d = t / 18432; local = t - d * 18432;
        src = dcn_w + (size_t)d * 36864; isGemm = true; Cin = 64; Cout = 64;
    }
    float vlo = 0.f, vhi = 0.f;
    if (isGemm) {
        const int r    = local & 1;
        const int lane = (local >> 1) & 31;
        const int mi   = (local >> 6) & 1;
        const int wM   = (local >> 7) & 1;
        const int chunk = local >> 8;
        const int g8 = chunk / 9, k = chunk - g8 * 9;
        const int co = wM * 32 + mi * 16 + (r << 3) + (lane >> 2);
        const int ci = 2 * (lane & 3);
        vlo = src[(size_t)co * 576 + (g8 * 8 + ci) * 9 + k];
        vhi = src[(size_t)co * 576 + (g8 * 8 + ci + 1) * 9 + k];
    } else {
        const int r    = local & 3;
        const int lane = (local >> 2) & 31;
        const int mi   = (local >> 7) & 1;
        const int wM   = (local >> 8) & 1;
        const int kx   = (local >> 9) % 3;
        const int t    = local / 1536;
        const int nci16 = Cin >> 4;
        const int cc = t % nci16;
        const int ky = (t / nci16) % 3;
        const int zb = t / (nci16 * 3);
        const int co = zb * 64 + wM * 32 + mi * 16 + ((r & 1) << 3) + (lane >> 2);
        const int ciP = cc * 16 + ((r >> 1) << 3) + 2 * (lane & 3);
        const int k = ky * 3 + kx;
        if (co < Cout) {
            vlo = src[((size_t)co * Cin + ciP) * 9 + k];
            vhi = src[((size_t)co * Cin + ciP + 1) * 9 + k];
        }
    }
    dst[gid] = pack_h2(vlo, vhi);
}

// ---------------- fp16 implicit-GEMM 3x3 SAME conv, 3-stage ring, pair-interleaved ----------------
// Block 256 thr = 8 warps (2M x 4N). Tile: 64 Cout x 128 px (one row). Chunk = (ky, 16 ci = 8 pair rows).
// smem input: u32 pair rows [pr(8)][136], px=0 at word 4, halos at words 3 / 132.
#define SPW 136
__global__ __launch_bounds__(256, 3) void conv3x3_tc2(
    const unsigned* __restrict__ in, const unsigned* __restrict__ wp,
    const float* __restrict__ bias, unsigned* __restrict__ out,
    const unsigned* __restrict__ addsrc, int Cin, int Cout, int flags)
{
    __shared__ __align__(16) unsigned sIn2[3][8 * SPW];
    __shared__ __align__(16) unsigned sWq[3][1536];

    const int row  = blockIdx.x;
    const int img  = blockIdx.y;
    const int zb   = blockIdx.z;
    const int coT  = zb << 6;
    const int tid  = threadIdx.x;
    const int warp = tid >> 5;
    const int lane = tid & 31;
    const int g    = lane >> 2, t4 = lane & 3;
    const int par  = g & 1;
    const int wM   = warp & 1,  wN = warp >> 1;
    const int nci16 = Cin >> 4;
    const int nch  = 3 * nci16;
    const int catMode = flags & 4;
    const int inPairs = (catMode ? 64 : Cin) >> 1;

    const uint32_t sInB = smem_u32(sIn2);
    const uint32_t sWB  = smem_u32(sWq);
    const unsigned* inImg  = in + (size_t)img * inPairs * HW;
    const unsigned* refImg = catMode ? in + (size_t)((img / 5) * 5 + 2) * 32 * HW : inImg;
    const unsigned* wpL  = wp + (size_t)zb * nch * 1536;
    const bool mValid    = (coT + wM * 32) < Cout;
    const int Cpairs     = Cout >> 1;

    float acc[2][4][4];
#pragma unroll
    for (int i = 0; i < 2; i++)
#pragma unroll
        for (int j = 0; j < 4; j++)
#pragma unroll
            for (int l = 0; l < 4; l++) acc[i][j][l] = 0.f;

    // halo words 3 and 132: 3buf x 8rows x 2 = 48
    if (tid < 48) {
        const int b = tid / 16, rem = tid & 15;
        sIn2[b][(rem >> 1) * SPW + ((rem & 1) ? 132 : 3)] = 0u;
    }

    // loadChunk takes pre-decomposed (ky, cc) — no per-call division
    auto loadChunk = [&](int c, int ky, int cc, int buf) {
        int gr = row + ky - 1;
        const unsigned rs = ((unsigned)gr < HH) ? 16u : 0u;
        if (gr < 0) gr = 0; else if (gr > HH - 1) gr = HH - 1;
        const unsigned* src;
        int prBase;
        if (catMode) {
            if (cc < 4) { src = refImg; prBase = cc * 8; }
            else        { src = inImg;  prBase = (cc - 4) * 8; }
        } else { src = inImg; prBase = cc * 8; }
        {
            const int pr = tid >> 5, j = tid & 31;
            cp16(sInB + (buf * 8 * SPW + pr * SPW + 4 + j * 4) * 4,
                 src + (size_t)(prBase + pr) * HW + gr * WW + j * 4, rs);
        }
        const unsigned* ws = wpL + (size_t)c * 1536;
#pragma unroll
        for (int i = tid; i < 384; i += 256)
            cp16(sWB + (buf * 1536 + 4 * i) * 4, ws + 4 * i, 16);
        cp_commit();
    };

    // prologue: 2 chunks in flight
    loadChunk(0, 0, 0, 0);
    loadChunk(1, 0, 1, 1);

    // incrementally-maintained (ky, cc) for the chunk we will load (c+2)
    int lky = (nci16 == 2) ? 1 : 0;
    int lcc = (nci16 == 2) ? 0 : 2;

    int bufC = 0;
    for (int c = 0; c < nch; c++) {
        if (c + 1 < nch) cp_wait1();
        else             cp_wait0();
        __syncthreads();

        if (c + 2 < nch) {
            int bufI = bufC + 2; if (bufI >= 3) bufI -= 3;
            loadChunk(c + 2, lky, lcc, bufI);
            if (++lcc == nci16) { lcc = 0; ++lky; }
        }

        if (mValid) {
            const unsigned* pw = sIn2[bufC];
            const unsigned* sWb = sWq[bufC];
            const int obase = t4 * SPW + 3 + wN * 32 + g;
#pragma unroll
            for (int kx = 0; kx < 3; kx++) {
                const uint4 A0 = *(const uint4*)&sWb[(kx * 4 + wM * 2 + 0) * 128 + lane * 4];
                const uint4 A1 = *(const uint4*)&sWb[(kx * 4 + wM * 2 + 1) * 128 + lane * 4];
#pragma unroll
                for (int ni = 0; ni < 4; ni++) {
                    const int o = obase + kx + ni * 8;
                    const unsigned b0 = pw[o];
                    const unsigned b1 = pw[o + 4 * SPW];
                    mma_f16_k16(acc[0][ni], A0, b0, b1);
                    mma_f16_k16(acc[1][ni], A1, b0, b1);
                }
            }
        }
        if (++bufC == 3) bufC = 0;
    }

    // ---- epilogue: shfl co-pair packing, u32 stores ----
    const int doRelu = flags & 1;
#pragma unroll
    for (int mi = 0; mi < 2; mi++) {
#pragma unroll
        for (int rr = 0; rr < 2; rr++) {
            const int cob2 = coT + wM * 32 + mi * 16 + rr * 8 + (g & ~1);
            const bool vld = cob2 < Cout;
            float2 bv = make_float2(0.f, 0.f);
            if (vld) bv = *(const float2*)&bias[cob2];
#pragma unroll
            for (int ni = 0; ni < 4; ni++) {
                const float v0 = acc[mi][ni][rr * 2 + 0];
                const float v1 = acc[mi][ni][rr * 2 + 1];
                const float o0 = __shfl_xor_sync(0xffffffffu, v0, 4);
                const float o1 = __shfl_xor_sync(0xffffffffu, v1, 4);
                float plo, phi;
                if (par == 0) { plo = v0; phi = o0; }
                else          { plo = o1; phi = v1; }
                if (vld) {
                    const int pxl = wN * 32 + 2 * t4 + ni * 8 + par;
                    const size_t w = ((size_t)img * Cpairs + (cob2 >> 1)) * HW + row * WW + pxl;
                    plo += bv.x; phi += bv.y;
                    if (addsrc) {
                        const __half2 r2 = *(const __half2*)&addsrc[w];
                        plo += __half2float(__low2half(r2));
                        phi += __half2float(__high2half(r2));
                    }
                    if (doRelu) { plo = fmaxf(plo, 0.f); phi = fmaxf(phi, 0.f); }
                    out[w] = pack_h2(plo, phi);
                }
            }
        }
    }
}

// ---------------- fused deformable-im2col + GEMM (Cout=64, K=576), 4-ring weights ----------------
__global__ __launch_bounds__(256, 3) void dcn_fused_kernel(
    const unsigned* __restrict__ wp,  // [72][256] prepped fp16x2
    const unsigned* __restrict__ x2,  // [img][32][HW]
    const unsigned* __restrict__ om2, // [img][108][HW]
    const float* __restrict__ bias,
    unsigned* __restrict__ out)       // [img][32][HW]
{
    __shared__ __align__(16) unsigned sB2[2][4 * SPW];
    __shared__ __align__(16) unsigned sW[4][256];

    const int pxb  = blockIdx.x << 7;
    const int img  = blockIdx.y;
    const int tid  = threadIdx.x;
    const int warp = tid >> 5;
    const int lane = tid & 31;
    const int g_   = lane >> 2, t4 = lane & 3;
    const int par  = g_ & 1;
    const int wM   = warp & 1,  wN = warp >> 1;
    const int pxl  = tid & 127;
    const int half_ = tid >> 7;
    const int h    = pxb >> 7;
    const int w    = pxl;

    const uint32_t sWB = smem_u32(sW);
    const unsigned* omj2 = om2 + (size_t)img * 108 * HW + pxb + pxl;
    const unsigned* xg2  = x2 + (size_t)img * 32 * HW;

    float acc[2][4][4];
#pragma unroll
    for (int i = 0; i < 2; i++)
#pragma unroll
        for (int j = 0; j < 4; j++)
#pragma unroll
            for (int l = 0; l < 4; l++) acc[i][j][l] = 0.f;

    unsigned rg[2][4];
    float fw[4];

    auto gatherIssue = [&](int c) {
        const int gg = c / 9, k = c - gg * 9;
        const int cp = c >> 1, sel = c & 1;
        const float dy = h2_get(omj2[(size_t)cp * HW], sel);
        const float dx = h2_get(omj2[(size_t)(36 + cp) * HW], sel);
        float m        = h2_get(omj2[(size_t)(72 + cp) * HW], sel);
        m = 1.f / (1.f + expf(-m));
        const float py  = (float)(h + k / 3 - 1) + dy;
        const float pxf = (float)(w + k % 3 - 1) + dx;
        const float y0f = floorf(py), x0f = floorf(pxf);
        const float wy = py - y0f, wx = pxf - x0f;
        const int y0 = (int)y0f, x0 = (int)x0f;
        const int y1 = y0 + 1,   x1 = x0 + 1;
        const bool vy0 = (y0 >= 0) & (y0 < HH), vy1 = (y1 >= 0) & (y1 < HH);
        const bool vx0 = (x0 >= 0) & (x0 < WW), vx1 = (x1 >= 0) & (x1 < WW);
        const int cy0 = min(max(y0, 0), HH - 1), cy1 = min(max(y1, 0), HH - 1);
        const int cx0 = min(max(x0, 0), WW - 1), cx1 = min(max(x1, 0), WW - 1);
        fw[0] = (1.f - wy) * (1.f - wx) * m * ((vy0 && vx0) ? 1.f : 0.f);
        fw[1] = (1.f - wy) * wx         * m * ((vy0 && vx1) ? 1.f : 0.f);
        fw[2] = wy * (1.f - wx)         * m * ((vy1 && vx0) ? 1.f : 0.f);
        fw[3] = wy * wx                 * m * ((vy1 && vx1) ? 1.f : 0.f);
        const int i00 = cy0 * WW + cx0, i01 = cy0 * WW + cx1;
        const int i10 = cy1 * WW + cx0, i11 = cy1 * WW + cx1;
        const unsigned* xp = xg2 + (size_t)(gg * 4 + half_ * 2) * HW;
#pragma unroll
        for (int pp = 0; pp < 2; pp++) {
            const unsigned* xc = xp + (size_t)pp * HW;
            rg[pp][0] = xc[i00];
            rg[pp][1] = xc[i01];
            rg[pp][2] = xc[i10];
            rg[pp][3] = xc[i11];
        }
    };
    auto stageW = [&](int c, int buf) {
        if (tid < 64)
            cp16(sWB + (buf * 256 + 4 * tid) * 4, wp + (size_t)c * 256 + 4 * tid, 16);
        cp_commit();
    };
    auto stsB = [&](int buf) {
#pragma unroll
        for (int pp = 0; pp < 2; pp++) {
            float lo = 0.f, hi = 0.f;
#pragma unroll
            for (int cr = 0; cr < 4; cr++) {
                const float2 f2 = __half22float2(*(__half2*)&rg[pp][cr]);
                lo += fw[cr] * f2.x;
                hi += fw[cr] * f2.y;
            }
            sB2[buf][(half_ * 2 + pp) * SPW + pxl] = pack_h2(lo, hi);
        }
    };

    // prologue: 3 weight chunks in flight; gather+sts chunk 0
    stageW(0, 0);
    stageW(1, 1);
    stageW(2, 2);
    gatherIssue(0);
    stsB(0);
    cp_wait2();          // group 0 complete
    __syncthreads();

    for (int c = 0; c < 72; c++) {
        if (c + 3 < 72) stageW(c + 3, (c + 3) & 3);
        if (c + 1 < 72) gatherIssue(c + 1);

        const unsigned* pb = sB2[c & 1];
        const unsigned* sWb = sW[c & 3];
        const uint2 A0 = *(const uint2*)&sWb[(wM * 2 + 0) * 64 + lane * 2];
        const uint2 A1 = *(const uint2*)&sWb[(wM * 2 + 1) * 64 + lane * 2];
        const int obase = t4 * SPW + wN * 32 + g_;
#pragma unroll
        for (int ni = 0; ni < 4; ni++) {
            const unsigned b0 = pb[obase + ni * 8];
            mma_f16_k8(acc[0][ni], A0, b0);
            mma_f16_k8(acc[1][ni], A1, b0);
        }
        if (c < 71) { stsB((c + 1) & 1); cp_wait2(); }
        __syncthreads();
    }

#pragma unroll
    for (int mi = 0; mi < 2; mi++) {
#pragma unroll
        for (int rr = 0; rr < 2; rr++) {
            const int cob2 = wM * 32 + mi * 16 + rr * 8 + (g_ & ~1);
            const float2 bv = *(const float2*)&bias[cob2];
#pragma unroll
            for (int ni = 0; ni < 4; ni++) {
                const float v0 = acc[mi][ni][rr * 2 + 0];
                const float v1 = acc[mi][ni][rr * 2 + 1];
                const float o0 = __shfl_xor_sync(0xffffffffu, v0, 4);
                const float o1 = __shfl_xor_sync(0xffffffffu, v1, 4);
                float plo, phi;
                if (par == 0) { plo = v0; phi = o0; }
                else          { plo = o1; phi = v1; }
                const int pxo = wN * 32 + 2 * t4 + ni * 8 + par;
                const size_t wdx = ((size_t)img * 32 + (cob2 >> 1)) * HW + pxb + pxo;
                out[wdx] = pack_h2(plo + bv.x, phi + bv.y);
            }
        }
    }
}

// ---------------- FFMA 3x3 conv (Cin=1 / Cout=1 cases), pair-layout aware ----------------
__global__ __launch_bounds__(256, 2) void conv3x3_kernel(
    const void* __restrict__ inRaw, const float* __restrict__ wt,
    const float* __restrict__ bias, void* __restrict__ outRaw,
    int Cin, int Cout, int doRelu, int inPair, int outPair)
{
    __shared__ __align__(16) float sIn[CHUNK][18][80];
    __shared__ __align__(16) float sW[CHUNK][9][16];

    const int tw  = blockIdx.x & 1;
    const int th  = blockIdx.x >> 1;
    const int img = blockIdx.y;
    const int cob = blockIdx.z * 16;
    const int tid = threadIdx.x;
    const int tx  = tid & 15;
    const int ty  = tid >> 4;

    const float* inF = (const float*)inRaw;
    const __half* inH = (const __half*)inRaw;
    float* outF = (float*)outRaw;
    unsigned* outP = (unsigned*)outRaw;

    float acc[4][16];
#pragma unroll
    for (int p = 0; p < 4; p++)
#pragma unroll
        for (int c = 0; c < 16; c++) acc[p][c] = 0.f;

    const int nch = (Cin + CHUNK - 1) / CHUNK;
    for (int cc = 0; cc < nch; cc++) {
        const int cin0 = cc * CHUNK;
        for (int idx = tid; idx < CHUNK * 18 * 66; idx += 256) {
            int ci  = idx / (18 * 66);
            int rem = idx - ci * (18 * 66);
            int r = rem / 66, c = rem - r * 66;
            int gr = th * 16 + r - 1;
            int gc = tw * 64 + c - 1;
            int cin = cin0 + ci;
            float v = 0.f;
            if (cin < Cin && gr >= 0 && gr < HH && gc >= 0 && gc < WW) {
                if (inPair) {
                    const size_t widx = ((size_t)img * (Cin >> 1) + (cin >> 1)) * HW + gr * WW + gc;
                    v = __half2float(inH[widx * 2 + (cin & 1)]);
                } else {
                    v = inF[((size_t)img * Cin + cin) * HW + gr * WW + gc];
                }
            }
            sIn[ci][r][c] = v;
        }
        for (int idx = tid; idx < CHUNK * 9 * 16; idx += 256) {
            int ci  = idx / 144;
            int rem = idx - ci * 144;
            int k = rem >> 4, co = rem & 15;
            int cin = cin0 + ci;
            float v = 0.f;
            if (cin < Cin && (cob + co) < Cout)
                v = wt[((size_t)(cob + co) * Cin + cin) * 9 + k];
            sW[ci][k][co] = v;
        }
        __syncthreads();

        for (int ci = 0; ci < CHUNK; ci++) {
#pragma unroll
            for (int k = 0; k < 9; k++) {
                const int ky = k / 3, kx = k - ky * 3;
                const float4 w0 = *(const float4*)&sW[ci][k][0];
                const float4 w1 = *(const float4*)&sW[ci][k][4];
                const float4 w2 = *(const float4*)&sW[ci][k][8];
                const float4 w3 = *(const float4*)&sW[ci][k][12];
                const float wv[16] = {w0.x, w0.y, w0.z, w0.w, w1.x, w1.y, w1.z, w1.w,
                                      w2.x, w2.y, w2.z, w2.w, w3.x, w3.y, w3.z, w3.w};
#pragma unroll
                for (int p = 0; p < 4; p++) {
                    const float xv = sIn[ci][ty + ky][tx + 16 * p + kx];
#pragma unroll
                    for (int co = 0; co < 16; co++)
                        acc[p][co] = fmaf(xv, wv[co], acc[p][co]);
                }
            }
        }
        __syncthreads();
    }

    const int row = th * 16 + ty;
    const int colb2 = tw * 64 + tx;
    if (outPair) {
#pragma unroll
        for (int co = 0; co < 16; co += 2) {
            const int oc = cob + co;
            if (oc + 1 < Cout) {
                const float b0 = bias[oc], b1 = bias[oc + 1];
#pragma unroll
                for (int p = 0; p < 4; p++) {
                    float v0 = acc[p][co] + b0;
                    float v1 = acc[p][co + 1] + b1;
                    if (doRelu) { v0 = fmaxf(v0, 0.f); v1 = fmaxf(v1, 0.f); }
                    outP[((size_t)img * (Cout >> 1) + (oc >> 1)) * HW + row * WW + colb2 + 16 * p]
                        = pack_h2(v0, v1);
                }
            }
        }
    } else {
#pragma unroll
        for (int co = 0; co < 16; co++) {
            const int oc = cob + co;
            if (oc < Cout) {
                const float b = bias[oc];
#pragma unroll
                for (int p = 0; p < 4; p++) {
                    float v = acc[p][co] + b;
                    if (doRelu) v = fmaxf(v, 0.f);
                    outF[((size_t)img * Cout + oc) * HW + row * WW + colb2 + 16 * p] = v;
                }
            }
        }
    }
}

// ---------------- host launcher ----------------
static inline void launch_conv_ffma(const void* in, const float* w, const float* b,
                                    void* out, int Cin, int Cout, int relu,
                                    int inPair, int outPair)
{
    dim3 grid(16, NIMG, (Cout + 15) / 16);
    conv3x3_kernel<<<grid, 256>>>(in, w, b, out, Cin, Cout, relu, inPair, outPair);
}

static inline void launch_conv_tc(const unsigned* in, const unsigned* wp, const float* b,
                                  unsigned* out, const unsigned* add,
                                  int Cin, int Cout, int flags)
{
    dim3 grid(HH, NIMG, (Cout + 63) / 64);
    conv3x3_tc2<<<grid, 256>>>(in, wp, b, out, add, Cin, Cout, flags);
}

extern "C" void kernel_launch(void* const* d_in, const int* in_sizes, int n_in,
                              void* d_out, int out_size)
{
    const float* x       = (const float*)d_in[0];
    const float* w_init  = (const float*)d_in[1];
    const float* b_init  = (const float*)d_in[2];
    const float* res_w1  = (const float*)d_in[3];
    const float* res_b1  = (const float*)d_in[4];
    const float* res_w2  = (const float*)d_in[5];
    const float* res_b2  = (const float*)d_in[6];
    const float* w_bn    = (const float*)d_in[7];
    const float* b_bn    = (const float*)d_in[8];
    const float* off_w   = (const float*)d_in[9];
    const float* off_b   = (const float*)d_in[10];
    const float* com_w   = (const float*)d_in[11];
    const float* com_b   = (const float*)d_in[12];
    const float* dcn_w   = (const float*)d_in[13];
    const float* dcn_b   = (const float*)d_in[14];
    const float* w_rec   = (const float*)d_in[15];
    const float* b_rec   = (const float*)d_in[16];
    float* out = (float*)d_out;

    unsigned *bufA, *bufB, *bufT, *obuf, *om, *wprep;
    cudaGetSymbolAddress((void**)&bufA, g_bufA);
    cudaGetSymbolAddress((void**)&bufB, g_bufB);
    cudaGetSymbolAddress((void**)&bufT, g_bufT);
    cudaGetSymbolAddress((void**)&obuf, g_off);
    cudaGetSymbolAddress((void**)&om,   g_om);
    cudaGetSymbolAddress((void**)&wprep, g_wprep);

    // ---- single fused weight prep ----
    prep_all_kernel<<<2592, 256>>>(res_w1, res_w2, w_bn, off_w, com_w, dcn_w, wprep);
    const unsigned* pw_r1[5]; const unsigned* pw_r2[5];
    for (int i = 0; i < 5; i++) { pw_r1[i] = wprep + (size_t)i * 18432; pw_r2[i] = wprep + (size_t)(5 + i) * 18432; }
    const unsigned* pw_bn = wprep + 184320;
    const unsigned* pw_off[4]; const unsigned* pw_com[4]; const unsigned* pw_gemm[4];
    for (int d = 0; d < 4; d++) {
        pw_off[d]  = wprep + 221184 + (size_t)d * 18432;
        pw_com[d]  = wprep + 294912 + (size_t)d * 73728;
        pw_gemm[d] = wprep + 589824 + (size_t)d * 18432;
    }

    // ---- network ----
    // 1) init conv + relu (Cin=1, FFMA): fp32 in -> pair-fp16 out
    launch_conv_ffma(x, w_init, b_init, bufA, 1, 64, 1, 0, 1);

    // 2) 5 residual blocks (fp16 MMA, pair layout)
    unsigned* cur = bufA;
    unsigned* nxt = bufB;
    for (int i = 0; i < 5; i++) {
        launch_conv_tc(cur, pw_r1[i], res_b1 + i * 64, bufT, nullptr, 64, 64, 1);
        launch_conv_tc(bufT, pw_r2[i], res_b2 + i * 64, nxt, cur, 64, 64, 0);
        unsigned* t = cur; cur = nxt; nxt = t;
    }
    unsigned* feat = cur;

    // 3) bottleneck conv over [ref | nei] (cat folded into loads)
    launch_conv_tc(feat, pw_bn, b_bn, bufA, nullptr, 128, 64, 4);

    // 4) four chained DCN stages
    dim3 ggemm(HW / 128, NIMG);
    auto dcn_stage = [&](const unsigned* xsrc, const unsigned* feaSrc, int di, unsigned* outBuf) {
        launch_conv_tc(feaSrc, pw_off[di], off_b + di * 64, obuf, nullptr, 64, 64, 0);
        launch_conv_tc(obuf, pw_com[di], com_b + di * 216, om, nullptr, 64, 216, 0);
        dcn_fused_kernel<<<ggemm, 256>>>(pw_gemm[di], xsrc, om, dcn_b + di * 64, outBuf);
    };

    dcn_stage(bufA, bufA, 0, bufT);   // fea = dcn(fea, o0)
    dcn_stage(bufT, bufT, 1, bufA);   // fea = dcn(fea, o1)
    dcn_stage(feat, bufA, 2, bufT);   // fea = dcn(nei, o2)
    dcn_stage(bufT, bufT, 3, bufA);   // aligned = dcn(fea, o3)

    // 5) reconstruction conv (Cout=1, FFMA): pair-fp16 in -> fp32 out
    launch_conv_ffma(bufA, w_rec, b_rec, out, 64, 1, 0, 1, 0);
}

// round 16
// speedup vs baseline: 1.0119x; 1.0119x over previous
#include <cuda_runtime.h>
#include <cuda_fp16.h>
#include <math.h>
#include <stdint.h>

#define HH 128
#define WW 128
#define HW 16384
#define NIMG 20
#define CHUNK 4

// ---------------- scratch: all activations channel-pair-interleaved u32 = half2(ci_even, ci_odd) ----------------
__device__ unsigned g_bufA[(size_t)NIMG * 32 * HW];
__device__ unsigned g_bufB[(size_t)NIMG * 32 * HW];
__device__ unsigned g_bufT[(size_t)NIMG * 32 * HW];
__device__ unsigned g_off [(size_t)NIMG * 32 * HW];
__device__ unsigned g_om  [(size_t)NIMG * 108 * HW];
__device__ unsigned g_wprep[663552];

// ---------------- helpers ----------------
__device__ __forceinline__ uint32_t smem_u32(const void* p) {
    uint32_t a;
    asm("{ .reg .u64 t; cvta.to.shared.u64 t, %1; cvt.u32.u64 %0, t; }" : "=r"(a) : "l"(p));
    return a;
}
__device__ __forceinline__ void cp16(uint32_t dst, const void* src, unsigned nbytes) {
    asm volatile("cp.async.cg.shared.global [%0], [%1], 16, %2;"
                 :: "r"(dst), "l"(src), "r"(nbytes) : "memory");
}
__device__ __forceinline__ void cp_commit() {
    asm volatile("cp.async.commit_group;" ::: "memory");
}
__device__ __forceinline__ void cp_wait1() {
    asm volatile("cp.async.wait_group 1;" ::: "memory");
}
__device__ __forceinline__ void cp_wait0() {
    asm volatile("cp.async.wait_group 0;" ::: "memory");
}
__device__ __forceinline__ void mma_f16_k16(float* c, uint4 a, unsigned b0, unsigned b1) {
    asm volatile(
        "mma.sync.aligned.m16n8k16.row.col.f32.f16.f16.f32 "
        "{%0,%1,%2,%3}, {%4,%5,%6,%7}, {%8,%9}, {%0,%1,%2,%3};"
        : "+f"(c[0]), "+f"(c[1]), "+f"(c[2]), "+f"(c[3])
        : "r"(a.x), "r"(a.y), "r"(a.z), "r"(a.w), "r"(b0), "r"(b1));
}
__device__ __forceinline__ void mma_f16_k8(float* c, uint2 a, unsigned b0) {
    asm volatile(
        "mma.sync.aligned.m16n8k8.row.col.f32.f16.f16.f32 "
        "{%0,%1,%2,%3}, {%4,%5}, {%6}, {%0,%1,%2,%3};"
        : "+f"(c[0]), "+f"(c[1]), "+f"(c[2]), "+f"(c[3])
        : "r"(a.x), "r"(a.y), "r"(b0));
}
__device__ __forceinline__ unsigned pack_h2(float lo, float hi) {
    __half2 h = __floats2half2_rn(lo, hi);
    return *(unsigned*)&h;
}
__device__ __forceinline__ float h2_get(unsigned w, int sel) {
    __half2 h = *(__half2*)&w;
    return sel ? __half2float(__high2half(h)) : __half2float(__low2half(h));
}

// ---------------- single fused weight-prep kernel ----------------
__global__ void prep_all_kernel(const float* __restrict__ res_w1, const float* __restrict__ res_w2,
                                const float* __restrict__ w_bn,  const float* __restrict__ off_w,
                                const float* __restrict__ com_w, const float* __restrict__ dcn_w,
                                unsigned* __restrict__ dst)
{
    const int gid = blockIdx.x * 256 + threadIdx.x;   // 663552 = 2592 * 256
    const float* src;
    int local, Cin, Cout;
    bool isGemm = false;
    if (gid < 184320) {
        const int ci = gid / 18432; local = gid - ci * 18432;
        src = (ci < 5) ? res_w1 + (size_t)ci * 36864 : res_w2 + (size_t)(ci - 5) * 36864;
        Cin = 64; Cout = 64;
    } else if (gid < 221184) {
        local = gid - 184320; src = w_bn; Cin = 128; Cout = 64;
    } else if (gid < 294912) {
        const int t = gid - 221184; const int d = t / 18432; local = t - d * 18432;
        src = off_w + (size_t)d * 36864; Cin = 64; Cout = 64;
    } else if (gid < 589824) {
        const int t = gid - 294912; const int d = t / 73728; local = t - d * 73728;
        src = com_w + (size_t)d * 124416; Cin = 64; Cout = 216;
    } else {
        const int t = gid - 589824; const int d = t / 18432; local = t - d * 18432;
        src = dcn_w + (size_t)d * 36864; isGemm = true; Cin = 64; Cout = 64;
    }
    float vlo = 0.f, vhi = 0.f;
    if (isGemm) {
        const int r    = local & 1;
        const int lane = (local >> 1) & 31;
        const int mi   = (local >> 6) & 1;
        const int wM   = (local >> 7) & 1;
        const int chunk = local >> 8;
        const int g8 = chunk / 9, k = chunk - g8 * 9;
        const int co = wM * 32 + mi * 16 + (r << 3) + (lane >> 2);
        const int ci = 2 * (lane & 3);
        vlo = src[(size_t)co * 576 + (g8 * 8 + ci) * 9 + k];
        vhi = src[(size_t)co * 576 + (g8 * 8 + ci + 1) * 9 + k];
    } else {
        const int r    = local & 3;
        const int lane = (local >> 2) & 31;
        const int mi   = (local >> 7) & 1;
        const int wM   = (local >> 8) & 1;
        const int kx   = (local >> 9) % 3;
        const int t    = local / 1536;
        const int nci16 = Cin >> 4;
        const int cc = t % nci16;
        const int ky = (t / nci16) % 3;
        const int zb = t / (nci16 * 3);
        const int co = zb * 64 + wM * 32 + mi * 16 + ((r & 1) << 3) + (lane >> 2);
        const int ciP = cc * 16 + ((r >> 1) << 3) + 2 * (lane & 3);
        const int k = ky * 3 + kx;
        if (co < Cout) {
            vlo = src[((size_t)co * Cin + ciP) * 9 + k];
            vhi = src[((size_t)co * Cin + ciP + 1) * 9 + k];
        }
    }
    dst[gid] = pack_h2(vlo, vhi);
}

// ---------------- fp16 implicit-GEMM 3x3 SAME conv, 3-stage ring, hoisted staging ----------------
// Block 256 thr = 8 warps (2M x 4N). Tile: 64 Cout x 128 px (one row). Chunk = (ky, 16 ci = 8 pair rows).
// smem input: u32 pair rows [pr(8)][136], px=0 at word 4, halos at words 3 / 132.
#define SPW 136
__global__ __launch_bounds__(256, 3) void conv3x3_tc2(
    const unsigned* __restrict__ in, const unsigned* __restrict__ wp,
    const float* __restrict__ bias, unsigned* __restrict__ out,
    const unsigned* __restrict__ addsrc, int Cin, int Cout, int flags)
{
    __shared__ __align__(16) unsigned sIn2[3][8 * SPW];
    __shared__ __align__(16) unsigned sWq[3][1536];

    const int row  = blockIdx.x;
    const int img  = blockIdx.y;
    const int zb   = blockIdx.z;
    const int coT  = zb << 6;
    const int tid  = threadIdx.x;
    const int warp = tid >> 5;
    const int lane = tid & 31;
    const int g    = lane >> 2, t4 = lane & 3;
    const int par  = g & 1;
    const int wM   = warp & 1,  wN = warp >> 1;
    const int nci16 = Cin >> 4;
    const int nch  = 3 * nci16;
    const int catMode = flags & 4;
    const int inPairs = (catMode ? 64 : Cin) >> 1;

    const uint32_t sInB = smem_u32(sIn2);
    const uint32_t sWB  = smem_u32(sWq);
    const unsigned* inImg  = in + (size_t)img * inPairs * HW;
    const unsigned* refImg = catMode ? in + (size_t)((img / 5) * 5 + 2) * 32 * HW : inImg;
    const unsigned* wpL  = wp + (size_t)zb * nch * 1536;
    const bool mValid    = (coT + wM * 32) < Cout;
    const int Cpairs     = Cout >> 1;

    float acc[2][4][4];
#pragma unroll
    for (int i = 0; i < 2; i++)
#pragma unroll
        for (int j = 0; j < 4; j++)
#pragma unroll
            for (int l = 0; l < 4; l++) acc[i][j][l] = 0.f;

    // halo words 3 and 132: 3buf x 8rows x 2 = 48
    if (tid < 48) {
        const int b = tid / 16, rem = tid & 15;
        sIn2[b][(rem >> 1) * SPW + ((rem & 1) ? 132 : 3)] = 0u;
    }

    // ---- thread-constant staging offsets (hoisted out of the chunk loop) ----
    const int spr = tid >> 5, sj = tid & 31;
    const int thrIn = spr * HW + sj * 4;                        // src word offset
    const uint32_t dstIn0 = sInB + (spr * SPW + 4 + sj * 4) * 4;
    const uint32_t dstW0  = sWB + tid * 16;
    const uint32_t dstW1  = dstW0 + 4096;                        // i = tid + 256
    const int tid4 = tid * 4;
    int grOff[3]; unsigned rsK[3];
#pragma unroll
    for (int ky = 0; ky < 3; ky++) {
        int gr = row + ky - 1;
        rsK[ky] = ((unsigned)gr < HH) ? 16u : 0u;
        gr = min(max(gr, 0), HH - 1);
        grOff[ky] = gr * WW;
    }

    auto issueChunk = [&](int c, int ky, int cc, int buf) {
        const unsigned* base = (catMode && cc < 4) ? refImg : inImg;
        const int prB = (catMode && cc >= 4) ? (cc - 4) * 8 : cc * 8;
        const unsigned* cb = base + prB * HW + grOff[ky];
        cp16(dstIn0 + buf * 4352, cb + thrIn, rsK[ky]);
        const unsigned* ws = wpL + c * 1536;
        cp16(dstW0 + buf * 6144, ws + tid4, 16);
        if (tid < 128) cp16(dstW1 + buf * 6144, ws + tid4 + 1024, 16);
        cp_commit();
    };

    // prologue: 2 chunks in flight
    issueChunk(0, 0, 0, 0);
    issueChunk(1, 0, 1, 1);

    // incrementally-maintained (ky, cc) for the chunk we will load (c+2)
    int lky = (nci16 == 2) ? 1 : 0;
    int lcc = (nci16 == 2) ? 0 : 2;

    int bufC = 0;
    for (int c = 0; c < nch; c++) {
        if (c + 1 < nch) cp_wait1();
        else             cp_wait0();
        __syncthreads();

        if (c + 2 < nch) {
            int bufI = bufC + 2; if (bufI >= 3) bufI -= 3;
            issueChunk(c + 2, lky, lcc, bufI);
            if (++lcc == nci16) { lcc = 0; ++lky; }
        }

        if (mValid) {
            const unsigned* pw = sIn2[bufC];
            const unsigned* sWb = sWq[bufC];
            const int obase = t4 * SPW + 3 + wN * 32 + g;
#pragma unroll
            for (int kx = 0; kx < 3; kx++) {
                const uint4 A0 = *(const uint4*)&sWb[(kx * 4 + wM * 2 + 0) * 128 + lane * 4];
                const uint4 A1 = *(const uint4*)&sWb[(kx * 4 + wM * 2 + 1) * 128 + lane * 4];
#pragma unroll
                for (int ni = 0; ni < 4; ni++) {
                    const int o = obase + kx + ni * 8;
                    const unsigned b0 = pw[o];
                    const unsigned b1 = pw[o + 4 * SPW];
                    mma_f16_k16(acc[0][ni], A0, b0, b1);
                    mma_f16_k16(acc[1][ni], A1, b0, b1);
                }
            }
        }
        if (++bufC == 3) bufC = 0;
    }

    // ---- epilogue: shfl co-pair packing, u32 stores ----
    const int doRelu = flags & 1;
#pragma unroll
    for (int mi = 0; mi < 2; mi++) {
#pragma unroll
        for (int rr = 0; rr < 2; rr++) {
            const int cob2 = coT + wM * 32 + mi * 16 + rr * 8 + (g & ~1);
            const bool vld = cob2 < Cout;
            float2 bv = make_float2(0.f, 0.f);
            if (vld) bv = *(const float2*)&bias[cob2];
#pragma unroll
            for (int ni = 0; ni < 4; ni++) {
                const float v0 = acc[mi][ni][rr * 2 + 0];
                const float v1 = acc[mi][ni][rr * 2 + 1];
                const float o0 = __shfl_xor_sync(0xffffffffu, v0, 4);
                const float o1 = __shfl_xor_sync(0xffffffffu, v1, 4);
                float plo, phi;
                if (par == 0) { plo = v0; phi = o0; }
                else          { plo = o1; phi = v1; }
                if (vld) {
                    const int pxl = wN * 32 + 2 * t4 + ni * 8 + par;
                    const size_t w = ((size_t)img * Cpairs + (cob2 >> 1)) * HW + row * WW + pxl;
                    plo += bv.x; phi += bv.y;
                    if (addsrc) {
                        const __half2 r2 = *(const __half2*)&addsrc[w];
                        plo += __half2float(__low2half(r2));
                        phi += __half2float(__high2half(r2));
                    }
                    if (doRelu) { plo = fmaxf(plo, 0.f); phi = fmaxf(phi, 0.f); }
                    out[w] = pack_h2(plo, phi);
                }
            }
        }
    }
}

// ---------------- fused deformable-im2col + GEMM (Cout=64, K=576), pair-interleaved (R14 form) ----------------
__global__ __launch_bounds__(256, 3) void dcn_fused_kernel(
    const unsigned* __restrict__ wp,  // [72][256] prepped fp16x2
    const unsigned* __restrict__ x2,  // [img][32][HW]
    const unsigned* __restrict__ om2, // [img][108][HW]
    const float* __restrict__ bias,
    unsigned* __restrict__ out)       // [img][32][HW]
{
    __shared__ __align__(16) unsigned sB2[2][4 * SPW];
    __shared__ __align__(16) unsigned sW[2][256];

    const int pxb  = blockIdx.x << 7;
    const int img  = blockIdx.y;
    const int tid  = threadIdx.x;
    const int warp = tid >> 5;
    const int lane = tid & 31;
    const int g_   = lane >> 2, t4 = lane & 3;
    const int par  = g_ & 1;
    const int wM   = warp & 1,  wN = warp >> 1;
    const int pxl  = tid & 127;
    const int half_ = tid >> 7;
    const int h    = pxb >> 7;
    const int w    = pxl;

    const uint32_t sWB = smem_u32(sW);
    const unsigned* omj2 = om2 + (size_t)img * 108 * HW + pxb + pxl;
    const unsigned* xg2  = x2 + (size_t)img * 32 * HW;

    float acc[2][4][4];
#pragma unroll
    for (int i = 0; i < 2; i++)
#pragma unroll
        for (int j = 0; j < 4; j++)
#pragma unroll
            for (int l = 0; l < 4; l++) acc[i][j][l] = 0.f;

    unsigned rg[2][4];
    float fw[4];

    auto gatherIssue = [&](int c) {
        const int gg = c / 9, k = c - gg * 9;
        const int cp = c >> 1, sel = c & 1;
        const float dy = h2_get(omj2[(size_t)cp * HW], sel);
        const float dx = h2_get(omj2[(size_t)(36 + cp) * HW], sel);
        float m        = h2_get(omj2[(size_t)(72 + cp) * HW], sel);
        m = 1.f / (1.f + expf(-m));
        const float py  = (float)(h + k / 3 - 1) + dy;
        const float pxf = (float)(w + k % 3 - 1) + dx;
        const float y0f = floorf(py), x0f = floorf(pxf);
        const float wy = py - y0f, wx = pxf - x0f;
        const int y0 = (int)y0f, x0 = (int)x0f;
        const int y1 = y0 + 1,   x1 = x0 + 1;
        const bool vy0 = (y0 >= 0) & (y0 < HH), vy1 = (y1 >= 0) & (y1 < HH);
        const bool vx0 = (x0 >= 0) & (x0 < WW), vx1 = (x1 >= 0) & (x1 < WW);
        const int cy0 = min(max(y0, 0), HH - 1), cy1 = min(max(y1, 0), HH - 1);
        const int cx0 = min(max(x0, 0), WW - 1), cx1 = min(max(x1, 0), WW - 1);
        fw[0] = (1.f - wy) * (1.f - wx) * m * ((vy0 && vx0) ? 1.f : 0.f);
        fw[1] = (1.f - wy) * wx         * m * ((vy0 && vx1) ? 1.f : 0.f);
        fw[2] = wy * (1.f - wx)         * m * ((vy1 && vx0) ? 1.f : 0.f);
        fw[3] = wy * wx                 * m * ((vy1 && vx1) ? 1.f : 0.f);
        const int i00 = cy0 * WW + cx0, i01 = cy0 * WW + cx1;
        const int i10 = cy1 * WW + cx0, i11 = cy1 * WW + cx1;
        const unsigned* xp = xg2 + (size_t)(gg * 4 + half_ * 2) * HW;
#pragma unroll
        for (int pp = 0; pp < 2; pp++) {
            const unsigned* xc = xp + (size_t)pp * HW;
            rg[pp][0] = xc[i00];
            rg[pp][1] = xc[i01];
            rg[pp][2] = xc[i10];
            rg[pp][3] = xc[i11];
        }
    };
    auto stageW = [&](int c, int buf) {
        if (tid < 64)
            cp16(sWB + (buf * 256 + 4 * tid) * 4, wp + (size_t)c * 256 + 4 * tid, 16);
        cp_commit();
    };
    auto stsB = [&](int buf) {
#pragma unroll
        for (int pp = 0; pp < 2; pp++) {
            float lo = 0.f, hi = 0.f;
#pragma unroll
            for (int cr = 0; cr < 4; cr++) {
                const float2 f2 = __half22float2(*(__half2*)&rg[pp][cr]);
                lo += fw[cr] * f2.x;
                hi += fw[cr] * f2.y;
            }
            sB2[buf][(half_ * 2 + pp) * SPW + pxl] = pack_h2(lo, hi);
        }
    };

    stageW(0, 0);
    gatherIssue(0);
    stsB(0);
    cp_wait0();
    __syncthreads();

    for (int c = 0; c < 72; c++) {
        const int buf = c & 1;
        if (c < 71) { stageW(c + 1, buf ^ 1); gatherIssue(c + 1); }
        const unsigned* pb = sB2[buf];
        const unsigned* sWb = sW[buf];
        const uint2 A0 = *(const uint2*)&sWb[(wM * 2 + 0) * 64 + lane * 2];
        const uint2 A1 = *(const uint2*)&sWb[(wM * 2 + 1) * 64 + lane * 2];
        const int obase = t4 * SPW + wN * 32 + g_;
#pragma unroll
        for (int ni = 0; ni < 4; ni++) {
            const unsigned b0 = pb[obase + ni * 8];
            mma_f16_k8(acc[0][ni], A0, b0);
            mma_f16_k8(acc[1][ni], A1, b0);
        }
        if (c < 71) { stsB(buf ^ 1); cp_wait0(); }
        __syncthreads();
    }

#pragma unroll
    for (int mi = 0; mi < 2; mi++) {
#pragma unroll
        for (int rr = 0; rr < 2; rr++) {
            const int cob2 = wM * 32 + mi * 16 + rr * 8 + (g_ & ~1);
            const float2 bv = *(const float2*)&bias[cob2];
#pragma unroll
            for (int ni = 0; ni < 4; ni++) {
                const float v0 = acc[mi][ni][rr * 2 + 0];
                const float v1 = acc[mi][ni][rr * 2 + 1];
                const float o0 = __shfl_xor_sync(0xffffffffu, v0, 4);
                const float o1 = __shfl_xor_sync(0xffffffffu, v1, 4);
                float plo, phi;
                if (par == 0) { plo = v0; phi = o0; }
                else          { plo = o1; phi = v1; }
                const int pxo = wN * 32 + 2 * t4 + ni * 8 + par;
                const size_t wdx = ((size_t)img * 32 + (cob2 >> 1)) * HW + pxb + pxo;
                out[wdx] = pack_h2(plo + bv.x, phi + bv.y);
            }
        }
    }
}

// ---------------- FFMA 3x3 conv (Cin=1 / Cout=1 cases), pair-layout aware ----------------
__global__ __launch_bounds__(256, 2) void conv3x3_kernel(
    const void* __restrict__ inRaw, const float* __restrict__ wt,
    const float* __restrict__ bias, void* __restrict__ outRaw,
    int Cin, int Cout, int doRelu, int inPair, int outPair)
{
    __shared__ __align__(16) float sIn[CHUNK][18][80];
    __shared__ __align__(16) float sW[CHUNK][9][16];

    const int tw  = blockIdx.x & 1;
    const int th  = blockIdx.x >> 1;
    const int img = blockIdx.y;
    const int cob = blockIdx.z * 16;
    const int tid = threadIdx.x;
    const int tx  = tid & 15;
    const int ty  = tid >> 4;

    const float* inF = (const float*)inRaw;
    const __half* inH = (const __half*)inRaw;
    float* outF = (float*)outRaw;
    unsigned* outP = (unsigned*)outRaw;

    float acc[4][16];
#pragma unroll
    for (int p = 0; p < 4; p++)
#pragma unroll
        for (int c = 0; c < 16; c++) acc[p][c] = 0.f;

    const int nch = (Cin + CHUNK - 1) / CHUNK;
    for (int cc = 0; cc < nch; cc++) {
        const int cin0 = cc * CHUNK;
        for (int idx = tid; idx < CHUNK * 18 * 66; idx += 256) {
            int ci  = idx / (18 * 66);
            int rem = idx - ci * (18 * 66);
            int r = rem / 66, c = rem - r * 66;
            int gr = th * 16 + r - 1;
            int gc = tw * 64 + c - 1;
            int cin = cin0 + ci;
            float v = 0.f;
            if (cin < Cin && gr >= 0 && gr < HH && gc >= 0 && gc < WW) {
                if (inPair) {
                    const size_t widx = ((size_t)img * (Cin >> 1) + (cin >> 1)) * HW + gr * WW + gc;
                    v = __half2float(inH[widx * 2 + (cin & 1)]);
                } else {
                    v = inF[((size_t)img * Cin + cin) * HW + gr * WW + gc];
                }
            }
            sIn[ci][r][c] = v;
        }
        for (int idx = tid; idx < CHUNK * 9 * 16; idx += 256) {
            int ci  = idx / 144;
            int rem = idx - ci * 144;
            int k = rem >> 4, co = rem & 15;
            int cin = cin0 + ci;
            float v = 0.f;
            if (cin < Cin && (cob + co) < Cout)
                v = wt[((size_t)(cob + co) * Cin + cin) * 9 + k];
            sW[ci][k][co] = v;
        }
        __syncthreads();

        for (int ci = 0; ci < CHUNK; ci++) {
#pragma unroll
            for (int k = 0; k < 9; k++) {
                const int ky = k / 3, kx = k - ky * 3;
                const float4 w0 = *(const float4*)&sW[ci][k][0];
                const float4 w1 = *(const float4*)&sW[ci][k][4];
                const float4 w2 = *(const float4*)&sW[ci][k][8];
                const float4 w3 = *(const float4*)&sW[ci][k][12];
                const float wv[16] = {w0.x, w0.y, w0.z, w0.w, w1.x, w1.y, w1.z, w1.w,
                                      w2.x, w2.y, w2.z, w2.w, w3.x, w3.y, w3.z, w3.w};
#pragma unroll
                for (int p = 0; p < 4; p++) {
                    const float xv = sIn[ci][ty + ky][tx + 16 * p + kx];
#pragma unroll
                    for (int co = 0; co < 16; co++)
                        acc[p][co] = fmaf(xv, wv[co], acc[p][co]);
                }
            }
        }
        __syncthreads();
    }

    const int row = th * 16 + ty;
    const int colb2 = tw * 64 + tx;
    if (outPair) {
#pragma unroll
        for (int co = 0; co < 16; co += 2) {
            const int oc = cob + co;
            if (oc + 1 < Cout) {
                const float b0 = bias[oc], b1 = bias[oc + 1];
#pragma unroll
                for (int p = 0; p < 4; p++) {
                    float v0 = acc[p][co] + b0;
                    float v1 = acc[p][co + 1] + b1;
                    if (doRelu) { v0 = fmaxf(v0, 0.f); v1 = fmaxf(v1, 0.f); }
                    outP[((size_t)img * (Cout >> 1) + (oc >> 1)) * HW + row * WW + colb2 + 16 * p]
                        = pack_h2(v0, v1);
                }
            }
        }
    } else {
#pragma unroll
        for (int co = 0; co < 16; co++) {
            const int oc = cob + co;
            if (oc < Cout) {
                const float b = bias[oc];
#pragma unroll
                for (int p = 0; p < 4; p++) {
                    float v = acc[p][co] + b;
                    if (doRelu) v = fmaxf(v, 0.f);
                    outF[((size_t)img * Cout + oc) * HW + row * WW + colb2 + 16 * p] = v;
                }
            }
        }
    }
}

// ---------------- host launcher ----------------
static inline void launch_conv_ffma(const void* in, const float* w, const float* b,
                                    void* out, int Cin, int Cout, int relu,
                                    int inPair, int outPair)
{
    dim3 grid(16, NIMG, (Cout + 15) / 16);
    conv3x3_kernel<<<grid, 256>>>(in, w, b, out, Cin, Cout, relu, inPair, outPair);
}

static inline void launch_conv_tc(const unsigned* in, const unsigned* wp, const float* b,
                                  unsigned* out, const unsigned* add,
                                  int Cin, int Cout, int flags)
{
    dim3 grid(HH, NIMG, (Cout + 63) / 64);
    conv3x3_tc2<<<grid, 256>>>(in, wp, b, out, add, Cin, Cout, flags);
}

extern "C" void kernel_launch(void* const* d_in, const int* in_sizes, int n_in,
                              void* d_out, int out_size)
{
    const float* x       = (const float*)d_in[0];
    const float* w_init  = (const float*)d_in[1];
    const float* b_init  = (const float*)d_in[2];
    const float* res_w1  = (const float*)d_in[3];
    const float* res_b1  = (const float*)d_in[4];
    const float* res_w2  = (const float*)d_in[5];
    const float* res_b2  = (const float*)d_in[6];
    const float* w_bn    = (const float*)d_in[7];
    const float* b_bn    = (const float*)d_in[8];
    const float* off_w   = (const float*)d_in[9];
    const float* off_b   = (const float*)d_in[10];
    const float* com_w   = (const float*)d_in[11];
    const float* com_b   = (const float*)d_in[12];
    const float* dcn_w   = (const float*)d_in[13];
    const float* dcn_b   = (const float*)d_in[14];
    const float* w_rec   = (const float*)d_in[15];
    const float* b_rec   = (const float*)d_in[16];
    float* out = (float*)d_out;

    unsigned *bufA, *bufB, *bufT, *obuf, *om, *wprep;
    cudaGetSymbolAddress((void**)&bufA, g_bufA);
    cudaGetSymbolAddress((void**)&bufB, g_bufB);
    cudaGetSymbolAddress((void**)&bufT, g_bufT);
    cudaGetSymbolAddress((void**)&obuf, g_off);
    cudaGetSymbolAddress((void**)&om,   g_om);
    cudaGetSymbolAddress((void**)&wprep, g_wprep);

    // ---- single fused weight prep ----
    prep_all_kernel<<<2592, 256>>>(res_w1, res_w2, w_bn, off_w, com_w, dcn_w, wprep);
    const unsigned* pw_r1[5]; const unsigned* pw_r2[5];
    for (int i = 0; i < 5; i++) { pw_r1[i] = wprep + (size_t)i * 18432; pw_r2[i] = wprep + (size_t)(5 + i) * 18432; }
    const unsigned* pw_bn = wprep + 184320;
    const unsigned* pw_off[4]; const unsigned* pw_com[4]; const unsigned* pw_gemm[4];
    for (int d = 0; d < 4; d++) {
        pw_off[d]  = wprep + 221184 + (size_t)d * 18432;
        pw_com[d]  = wprep + 294912 + (size_t)d * 73728;
        pw_gemm[d] = wprep + 589824 + (size_t)d * 18432;
    }

    // ---- network ----
    // 1) init conv + relu (Cin=1, FFMA): fp32 in -> pair-fp16 out
    launch_conv_ffma(x, w_init, b_init, bufA, 1, 64, 1, 0, 1);

    // 2) 5 residual blocks (fp16 MMA, pair layout)
    unsigned* cur = bufA;
    unsigned* nxt = bufB;
    for (int i = 0; i < 5; i++) {
        launch_conv_tc(cur, pw_r1[i], res_b1 + i * 64, bufT, nullptr, 64, 64, 1);
        launch_conv_tc(bufT, pw_r2[i], res_b2 + i * 64, nxt, cur, 64, 64, 0);
        unsigned* t = cur; cur = nxt; nxt = t;
    }
    unsigned* feat = cur;

    // 3) bottleneck conv over [ref | nei] (cat folded into loads)
    launch_conv_tc(feat, pw_bn, b_bn, bufA, nullptr, 128, 64, 4);

    // 4) four chained DCN stages
    dim3 ggemm(HW / 128, NIMG);
    auto dcn_stage = [&](const unsigned* xsrc, const unsigned* feaSrc, int di, unsigned* outBuf) {
        launch_conv_tc(feaSrc, pw_off[di], off_b + di * 64, obuf, nullptr, 64, 64, 0);
        launch_conv_tc(obuf, pw_com[di], com_b + di * 216, om, nullptr, 64, 216, 0);
        dcn_fused_kernel<<<ggemm, 256>>>(pw_gemm[di], xsrc, om, dcn_b + di * 64, outBuf);
    };

    dcn_stage(bufA, bufA, 0, bufT);   // fea = dcn(fea, o0)
    dcn_stage(bufT, bufT, 1, bufA);   // fea = dcn(fea, o1)
    dcn_stage(feat, bufA, 2, bufT);   // fea = dcn(nei, o2)
    dcn_stage(bufT, bufT, 3, bufA);   // aligned = dcn(fea, o3)

    // 5) reconstruction conv (Cout=1, FFMA): pair-fp16 in -> fp32 out
    launch_conv_ffma(bufA, w_rec, b_rec, out, 64, 1, 0, 1, 0);
}

// round 17
// speedup vs baseline: 1.0178x; 1.0058x over previous
#include <cuda_runtime.h>
#include <cuda_fp16.h>
#include <math.h>
#include <stdint.h>

#define HH 128
#define WW 128
#define HW 16384
#define NIMG 20
#define CHUNK 4

// ---------------- scratch: all activations channel-pair-interleaved u32 = half2(ci_even, ci_odd) ----------------
__device__ unsigned g_bufA[(size_t)NIMG * 32 * HW];
__device__ unsigned g_bufB[(size_t)NIMG * 32 * HW];
__device__ unsigned g_bufT[(size_t)NIMG * 32 * HW];
__device__ unsigned g_off [(size_t)NIMG * 32 * HW];
__device__ unsigned g_om  [(size_t)NIMG * 108 * HW];
__device__ unsigned g_wprep[663552];

// ---------------- helpers ----------------
__device__ __forceinline__ uint32_t smem_u32(const void* p) {
    uint32_t a;
    asm("{ .reg .u64 t; cvta.to.shared.u64 t, %1; cvt.u32.u64 %0, t; }" : "=r"(a) : "l"(p));
    return a;
}
__device__ __forceinline__ void cp16(uint32_t dst, const void* src, unsigned nbytes) {
    asm volatile("cp.async.cg.shared.global [%0], [%1], 16, %2;"
                 :: "r"(dst), "l"(src), "r"(nbytes) : "memory");
}
__device__ __forceinline__ void cp_commit() {
    asm volatile("cp.async.commit_group;" ::: "memory");
}
__device__ __forceinline__ void cp_wait1() {
    asm volatile("cp.async.wait_group 1;" ::: "memory");
}
__device__ __forceinline__ void cp_wait0() {
    asm volatile("cp.async.wait_group 0;" ::: "memory");
}
__device__ __forceinline__ void mma_f16_k16(float* c, uint4 a, unsigned b0, unsigned b1) {
    asm volatile(
        "mma.sync.aligned.m16n8k16.row.col.f32.f16.f16.f32 "
        "{%0,%1,%2,%3}, {%4,%5,%6,%7}, {%8,%9}, {%0,%1,%2,%3};"
        : "+f"(c[0]), "+f"(c[1]), "+f"(c[2]), "+f"(c[3])
        : "r"(a.x), "r"(a.y), "r"(a.z), "r"(a.w), "r"(b0), "r"(b1));
}
__device__ __forceinline__ void mma_f16_k8(float* c, uint2 a, unsigned b0) {
    asm volatile(
        "mma.sync.aligned.m16n8k8.row.col.f32.f16.f16.f32 "
        "{%0,%1,%2,%3}, {%4,%5}, {%6}, {%0,%1,%2,%3};"
        : "+f"(c[0]), "+f"(c[1]), "+f"(c[2]), "+f"(c[3])
        : "r"(a.x), "r"(a.y), "r"(b0));
}
__device__ __forceinline__ unsigned pack_h2(float lo, float hi) {
    __half2 h = __floats2half2_rn(lo, hi);
    return *(unsigned*)&h;
}
__device__ __forceinline__ float h2_get(unsigned w, int sel) {
    __half2 h = *(__half2*)&w;
    return sel ? __half2float(__high2half(h)) : __half2float(__low2half(h));
}

// ---------------- single fused weight-prep kernel ----------------
__global__ void prep_all_kernel(const float* __restrict__ res_w1, const float* __restrict__ res_w2,
                                const float* __restrict__ w_bn,  const float* __restrict__ off_w,
                                const float* __restrict__ com_w, const float* __restrict__ dcn_w,
                                unsigned* __restrict__ dst)
{
    const int gid = blockIdx.x * 256 + threadIdx.x;   // 663552 = 2592 * 256
    const float* src;
    int local, Cin, Cout;
    bool isGemm = false;
    if (gid < 184320) {
        const int ci = gid / 18432; local = gid - ci * 18432;
        src = (ci < 5) ? res_w1 + (size_t)ci * 36864 : res_w2 + (size_t)(ci - 5) * 36864;
        Cin = 64; Cout = 64;
    } else if (gid < 221184) {
        local = gid - 184320; src = w_bn; Cin = 128; Cout = 64;
    } else if (gid < 294912) {
        const int t = gid - 221184; const int d = t / 18432; local = t - d * 18432;
        src = off_w + (size_t)d * 36864; Cin = 64; Cout = 64;
    } else if (gid < 589824) {
        const int t = gid - 294912; const int d = t / 73728; local = t - d * 73728;
        src = com_w + (size_t)d * 124416; Cin = 64; Cout = 216;
    } else {
        const int t = gid - 589824; const int d = t / 18432; local = t - d * 18432;
        src = dcn_w + (size_t)d * 36864; isGemm = true; Cin = 64; Cout = 64;
    }
    float vlo = 0.f, vhi = 0.f;
    if (isGemm) {
        const int r    = local & 1;
        const int lane = (local >> 1) & 31;
        const int mi   = (local >> 6) & 1;
        const int wM   = (local >> 7) & 1;
        const int chunk = local >> 8;
        const int g8 = chunk / 9, k = chunk - g8 * 9;
        const int co = wM * 32 + mi * 16 + (r << 3) + (lane >> 2);
        const int ci = 2 * (lane & 3);
        vlo = src[(size_t)co * 576 + (g8 * 8 + ci) * 9 + k];
        vhi = src[(size_t)co * 576 + (g8 * 8 + ci + 1) * 9 + k];
    } else {
        const int r    = local & 3;
        const int lane = (local >> 2) & 31;
        const int mi   = (local >> 7) & 1;
        const int wM   = (local >> 8) & 1;
        const int kx   = (local >> 9) % 3;
        const int t    = local / 1536;
        const int nci16 = Cin >> 4;
        const int cc = t % nci16;
        const int ky = (t / nci16) % 3;
        const int zb = t / (nci16 * 3);
        const int co = zb * 64 + wM * 32 + mi * 16 + ((r & 1) << 3) + (lane >> 2);
        const int ciP = cc * 16 + ((r >> 1) << 3) + 2 * (lane & 3);
        const int k = ky * 3 + kx;
        if (co < Cout) {
            vlo = src[((size_t)co * Cin + ciP) * 9 + k];
            vhi = src[((size_t)co * Cin + ciP + 1) * 9 + k];
        }
    }
    dst[gid] = pack_h2(vlo, vhi);
}

// ---------------- fp16 implicit-GEMM 3x3 SAME conv, 3-stage ring (R15-measured form) ----------------
// Block 256 thr = 8 warps (2M x 4N). Tile: 64 Cout x 128 px (one row). Chunk = (ky, 16 ci = 8 pair rows).
// smem input: u32 pair rows [pr(8)][136], px=0 at word 4, halos at words 3 / 132.
#define SPW 136
__global__ __launch_bounds__(256, 3) void conv3x3_tc2(
    const unsigned* __restrict__ in, const unsigned* __restrict__ wp,
    const float* __restrict__ bias, unsigned* __restrict__ out,
    const unsigned* __restrict__ addsrc, int Cin, int Cout, int flags)
{
    __shared__ __align__(16) unsigned sIn2[3][8 * SPW];
    __shared__ __align__(16) unsigned sWq[3][1536];

    const int row  = blockIdx.x;
    const int img  = blockIdx.y;
    const int zb   = blockIdx.z;
    const int coT  = zb << 6;
    const int tid  = threadIdx.x;
    const int warp = tid >> 5;
    const int lane = tid & 31;
    const int g    = lane >> 2, t4 = lane & 3;
    const int par  = g & 1;
    const int wM   = warp & 1,  wN = warp >> 1;
    const int nci16 = Cin >> 4;
    const int nch  = 3 * nci16;
    const int catMode = flags & 4;
    const int inPairs = (catMode ? 64 : Cin) >> 1;

    const uint32_t sInB = smem_u32(sIn2);
    const uint32_t sWB  = smem_u32(sWq);
    const unsigned* inImg  = in + (size_t)img * inPairs * HW;
    const unsigned* refImg = catMode ? in + (size_t)((img / 5) * 5 + 2) * 32 * HW : inImg;
    const unsigned* wpL  = wp + (size_t)zb * nch * 1536;
    const bool mValid    = (coT + wM * 32) < Cout;
    const int Cpairs     = Cout >> 1;

    float acc[2][4][4];
#pragma unroll
    for (int i = 0; i < 2; i++)
#pragma unroll
        for (int j = 0; j < 4; j++)
#pragma unroll
            for (int l = 0; l < 4; l++) acc[i][j][l] = 0.f;

    // halo words 3 and 132: 3buf x 8rows x 2 = 48
    if (tid < 48) {
        const int b = tid / 16, rem = tid & 15;
        sIn2[b][(rem >> 1) * SPW + ((rem & 1) ? 132 : 3)] = 0u;
    }

    // loadChunk takes pre-decomposed (ky, cc) — no per-call division
    auto loadChunk = [&](int c, int ky, int cc, int buf) {
        int gr = row + ky - 1;
        const unsigned rs = ((unsigned)gr < HH) ? 16u : 0u;
        if (gr < 0) gr = 0; else if (gr > HH - 1) gr = HH - 1;
        const unsigned* src;
        int prBase;
        if (catMode) {
            if (cc < 4) { src = refImg; prBase = cc * 8; }
            else        { src = inImg;  prBase = (cc - 4) * 8; }
        } else { src = inImg; prBase = cc * 8; }
        {
            const int pr = tid >> 5, j = tid & 31;
            cp16(sInB + (buf * 8 * SPW + pr * SPW + 4 + j * 4) * 4,
                 src + (size_t)(prBase + pr) * HW + gr * WW + j * 4, rs);
        }
        const unsigned* ws = wpL + (size_t)c * 1536;
#pragma unroll
        for (int i = tid; i < 384; i += 256)
            cp16(sWB + (buf * 1536 + 4 * i) * 4, ws + 4 * i, 16);
        cp_commit();
    };

    // prologue: 2 chunks in flight
    loadChunk(0, 0, 0, 0);
    loadChunk(1, 0, 1, 1);

    // incrementally-maintained (ky, cc) for the chunk we will load (c+2)
    int lky = (nci16 == 2) ? 1 : 0;
    int lcc = (nci16 == 2) ? 0 : 2;

    int bufC = 0;
    for (int c = 0; c < nch; c++) {
        if (c + 1 < nch) cp_wait1();
        else             cp_wait0();
        __syncthreads();

        if (c + 2 < nch) {
            int bufI = bufC + 2; if (bufI >= 3) bufI -= 3;
            loadChunk(c + 2, lky, lcc, bufI);
            if (++lcc == nci16) { lcc = 0; ++lky; }
        }

        if (mValid) {
            const unsigned* pw = sIn2[bufC];
            const unsigned* sWb = sWq[bufC];
            const int obase = t4 * SPW + 3 + wN * 32 + g;
#pragma unroll
            for (int kx = 0; kx < 3; kx++) {
                const uint4 A0 = *(const uint4*)&sWb[(kx * 4 + wM * 2 + 0) * 128 + lane * 4];
                const uint4 A1 = *(const uint4*)&sWb[(kx * 4 + wM * 2 + 1) * 128 + lane * 4];
#pragma unroll
                for (int ni = 0; ni < 4; ni++) {
                    const int o = obase + kx + ni * 8;
                    const unsigned b0 = pw[o];
                    const unsigned b1 = pw[o + 4 * SPW];
                    mma_f16_k16(acc[0][ni], A0, b0, b1);
                    mma_f16_k16(acc[1][ni], A1, b0, b1);
                }
            }
        }
        if (++bufC == 3) bufC = 0;
    }

    // ---- epilogue: shfl co-pair packing, u32 stores ----
    const int doRelu = flags & 1;
#pragma unroll
    for (int mi = 0; mi < 2; mi++) {
#pragma unroll
        for (int rr = 0; rr < 2; rr++) {
            const int cob2 = coT + wM * 32 + mi * 16 + rr * 8 + (g & ~1);
            const bool vld = cob2 < Cout;
            float2 bv = make_float2(0.f, 0.f);
            if (vld) bv = *(const float2*)&bias[cob2];
#pragma unroll
            for (int ni = 0; ni < 4; ni++) {
                const float v0 = acc[mi][ni][rr * 2 + 0];
                const float v1 = acc[mi][ni][rr * 2 + 1];
                const float o0 = __shfl_xor_sync(0xffffffffu, v0, 4);
                const float o1 = __shfl_xor_sync(0xffffffffu, v1, 4);
                float plo, phi;
                if (par == 0) { plo = v0; phi = o0; }
                else          { plo = o1; phi = v1; }
                if (vld) {
                    const int pxl = wN * 32 + 2 * t4 + ni * 8 + par;
                    const size_t w = ((size_t)img * Cpairs + (cob2 >> 1)) * HW + row * WW + pxl;
                    plo += bv.x; phi += bv.y;
                    if (addsrc) {
                        const __half2 r2 = *(const __half2*)&addsrc[w];
                        plo += __half2float(__low2half(r2));
                        phi += __half2float(__high2half(r2));
                    }
                    if (doRelu) { plo = fmaxf(plo, 0.f); phi = fmaxf(phi, 0.f); }
                    out[w] = pack_h2(plo, phi);
                }
            }
        }
    }
}

// ---------------- fused deformable-im2col + GEMM (Cout=64, K=576), pair-interleaved (R14 form) ----------------
__global__ __launch_bounds__(256, 3) void dcn_fused_kernel(
    const unsigned* __restrict__ wp,  // [72][256] prepped fp16x2
    const unsigned* __restrict__ x2,  // [img][32][HW]
    const unsigned* __restrict__ om2, // [img][108][HW]
    const float* __restrict__ bias,
    unsigned* __restrict__ out)       // [img][32][HW]
{
    __shared__ __align__(16) unsigned sB2[2][4 * SPW];
    __shared__ __align__(16) unsigned sW[2][256];

    const int pxb  = blockIdx.x << 7;
    const int img  = blockIdx.y;
    const int tid  = threadIdx.x;
    const int warp = tid >> 5;
    const int lane = tid & 31;
    const int g_   = lane >> 2, t4 = lane & 3;
    const int par  = g_ & 1;
    const int wM   = warp & 1,  wN = warp >> 1;
    const int pxl  = tid & 127;
    const int half_ = tid >> 7;
    const int h    = pxb >> 7;
    const int w    = pxl;

    const uint32_t sWB = smem_u32(sW);
    const unsigned* omj2 = om2 + (size_t)img * 108 * HW + pxb + pxl;
    const unsigned* xg2  = x2 + (size_t)img * 32 * HW;

    float acc[2][4][4];
#pragma unroll
    for (int i = 0; i < 2; i++)
#pragma unroll
        for (int j = 0; j < 4; j++)
#pragma unroll
            for (int l = 0; l < 4; l++) acc[i][j][l] = 0.f;

    unsigned rg[2][4];
    float fw[4];

    auto gatherIssue = [&](int c) {
        const int gg = c / 9, k = c - gg * 9;
        const int cp = c >> 1, sel = c & 1;
        const float dy = h2_get(omj2[(size_t)cp * HW], sel);
        const float dx = h2_get(omj2[(size_t)(36 + cp) * HW], sel);
        float m        = h2_get(omj2[(size_t)(72 + cp) * HW], sel);
        m = 1.f / (1.f + expf(-m));
        const float py  = (float)(h + k / 3 - 1) + dy;
        const float pxf = (float)(w + k % 3 - 1) + dx;
        const float y0f = floorf(py), x0f = floorf(pxf);
        const float wy = py - y0f, wx = pxf - x0f;
        const int y0 = (int)y0f, x0 = (int)x0f;
        const int y1 = y0 + 1,   x1 = x0 + 1;
        const bool vy0 = (y0 >= 0) & (y0 < HH), vy1 = (y1 >= 0) & (y1 < HH);
        const bool vx0 = (x0 >= 0) & (x0 < WW), vx1 = (x1 >= 0) & (x1 < WW);
        const int cy0 = min(max(y0, 0), HH - 1), cy1 = min(max(y1, 0), HH - 1);
        const int cx0 = min(max(x0, 0), WW - 1), cx1 = min(max(x1, 0), WW - 1);
        fw[0] = (1.f - wy) * (1.f - wx) * m * ((vy0 && vx0) ? 1.f : 0.f);
        fw[1] = (1.f - wy) * wx         * m * ((vy0 && vx1) ? 1.f : 0.f);
        fw[2] = wy * (1.f - wx)         * m * ((vy1 && vx0) ? 1.f : 0.f);
        fw[3] = wy * wx                 * m * ((vy1 && vx1) ? 1.f : 0.f);
        const int i00 = cy0 * WW + cx0, i01 = cy0 * WW + cx1;
        const int i10 = cy1 * WW + cx0, i11 = cy1 * WW + cx1;
        const unsigned* xp = xg2 + (size_t)(gg * 4 + half_ * 2) * HW;
#pragma unroll
        for (int pp = 0; pp < 2; pp++) {
            const unsigned* xc = xp + (size_t)pp * HW;
            rg[pp][0] = xc[i00];
            rg[pp][1] = xc[i01];
            rg[pp][2] = xc[i10];
            rg[pp][3] = xc[i11];
        }
    };
    auto stageW = [&](int c, int buf) {
        if (tid < 64)
            cp16(sWB + (buf * 256 + 4 * tid) * 4, wp + (size_t)c * 256 + 4 * tid, 16);
        cp_commit();
    };
    auto stsB = [&](int buf) {
#pragma unroll
        for (int pp = 0; pp < 2; pp++) {
            float lo = 0.f, hi = 0.f;
#pragma unroll
            for (int cr = 0; cr < 4; cr++) {
                const float2 f2 = __half22float2(*(__half2*)&rg[pp][cr]);
                lo += fw[cr] * f2.x;
                hi += fw[cr] * f2.y;
            }
            sB2[buf][(half_ * 2 + pp) * SPW + pxl] = pack_h2(lo, hi);
        }
    };

    stageW(0, 0);
    gatherIssue(0);
    stsB(0);
    cp_wait0();
    __syncthreads();

    for (int c = 0; c < 72; c++) {
        const int buf = c & 1;
        if (c < 71) { stageW(c + 1, buf ^ 1); gatherIssue(c + 1); }
        const unsigned* pb = sB2[buf];
        const unsigned* sWb = sW[buf];
        const uint2 A0 = *(const uint2*)&sWb[(wM * 2 + 0) * 64 + lane * 2];
        const uint2 A1 = *(const uint2*)&sWb[(wM * 2 + 1) * 64 + lane * 2];
        const int obase = t4 * SPW + wN * 32 + g_;
#pragma unroll
        for (int ni = 0; ni < 4; ni++) {
            const unsigned b0 = pb[obase + ni * 8];
            mma_f16_k8(acc[0][ni], A0, b0);
            mma_f16_k8(acc[1][ni], A1, b0);
        }
        if (c < 71) { stsB(buf ^ 1); cp_wait0(); }
        __syncthreads();
    }

#pragma unroll
    for (int mi = 0; mi < 2; mi++) {
#pragma unroll
        for (int rr = 0; rr < 2; rr++) {
            const int cob2 = wM * 32 + mi * 16 + rr * 8 + (g_ & ~1);
            const float2 bv = *(const float2*)&bias[cob2];
#pragma unroll
            for (int ni = 0; ni < 4; ni++) {
                const float v0 = acc[mi][ni][rr * 2 + 0];
                const float v1 = acc[mi][ni][rr * 2 + 1];
                const float o0 = __shfl_xor_sync(0xffffffffu, v0, 4);
                const float o1 = __shfl_xor_sync(0xffffffffu, v1, 4);
                float plo, phi;
                if (par == 0) { plo = v0; phi = o0; }
                else          { plo = o1; phi = v1; }
                const int pxo = wN * 32 + 2 * t4 + ni * 8 + par;
                const size_t wdx = ((size_t)img * 32 + (cob2 >> 1)) * HW + pxb + pxo;
                out[wdx] = pack_h2(plo + bv.x, phi + bv.y);
            }
        }
    }
}

// ---------------- FFMA 3x3 conv (Cin=1 / Cout=1 cases), pair-layout aware ----------------
__global__ __launch_bounds__(256, 2) void conv3x3_kernel(
    const void* __restrict__ inRaw, const float* __restrict__ wt,
    const float* __restrict__ bias, void* __restrict__ outRaw,
    int Cin, int Cout, int doRelu, int inPair, int outPair)
{
    __shared__ __align__(16) float sIn[CHUNK][18][80];
    __shared__ __align__(16) float sW[CHUNK][9][16];

    const int tw  = blockIdx.x & 1;
    const int th  = blockIdx.x >> 1;
    const int img = blockIdx.y;
    const int cob = blockIdx.z * 16;
    const int tid = threadIdx.x;
    const int tx  = tid & 15;
    const int ty  = tid >> 4;

    const float* inF = (const float*)inRaw;
    const __half* inH = (const __half*)inRaw;
    float* outF = (float*)outRaw;
    unsigned* outP = (unsigned*)outRaw;

    float acc[4][16];
#pragma unroll
    for (int p = 0; p < 4; p++)
#pragma unroll
        for (int c = 0; c < 16; c++) acc[p][c] = 0.f;

    const int nch = (Cin + CHUNK - 1) / CHUNK;
    for (int cc = 0; cc < nch; cc++) {
        const int cin0 = cc * CHUNK;
        for (int idx = tid; idx < CHUNK * 18 * 66; idx += 256) {
            int ci  = idx / (18 * 66);
            int rem = idx - ci * (18 * 66);
            int r = rem / 66, c = rem - r * 66;
            int gr = th * 16 + r - 1;
            int gc = tw * 64 + c - 1;
            int cin = cin0 + ci;
            float v = 0.f;
            if (cin < Cin && gr >= 0 && gr < HH && gc >= 0 && gc < WW) {
                if (inPair) {
                    const size_t widx = ((size_t)img * (Cin >> 1) + (cin >> 1)) * HW + gr * WW + gc;
                    v = __half2float(inH[widx * 2 + (cin & 1)]);
                } else {
                    v = inF[((size_t)img * Cin + cin) * HW + gr * WW + gc];
                }
            }
            sIn[ci][r][c] = v;
        }
        for (int idx = tid; idx < CHUNK * 9 * 16; idx += 256) {
            int ci  = idx / 144;
            int rem = idx - ci * 144;
            int k = rem >> 4, co = rem & 15;
            int cin = cin0 + ci;
            float v = 0.f;
            if (cin < Cin && (cob + co) < Cout)
                v = wt[((size_t)(cob + co) * Cin + cin) * 9 + k];
            sW[ci][k][co] = v;
        }
        __syncthreads();

        for (int ci = 0; ci < CHUNK; ci++) {
#pragma unroll
            for (int k = 0; k < 9; k++) {
                const int ky = k / 3, kx = k - ky * 3;
                const float4 w0 = *(const float4*)&sW[ci][k][0];
                const float4 w1 = *(const float4*)&sW[ci][k][4];
                const float4 w2 = *(const float4*)&sW[ci][k][8];
                const float4 w3 = *(const float4*)&sW[ci][k][12];
                const float wv[16] = {w0.x, w0.y, w0.z, w0.w, w1.x, w1.y, w1.z, w1.w,
                                      w2.x, w2.y, w2.z, w2.w, w3.x, w3.y, w3.z, w3.w};
#pragma unroll
                for (int p = 0; p < 4; p++) {
                    const float xv = sIn[ci][ty + ky][tx + 16 * p + kx];
#pragma unroll
                    for (int co = 0; co < 16; co++)
                        acc[p][co] = fmaf(xv, wv[co], acc[p][co]);
                }
            }
        }
        __syncthreads();
    }

    const int row = th * 16 + ty;
    const int colb2 = tw * 64 + tx;
    if (outPair) {
#pragma unroll
        for (int co = 0; co < 16; co += 2) {
            const int oc = cob + co;
            if (oc + 1 < Cout) {
                const float b0 = bias[oc], b1 = bias[oc + 1];
#pragma unroll
                for (int p = 0; p < 4; p++) {
                    float v0 = acc[p][co] + b0;
                    float v1 = acc[p][co + 1] + b1;
                    if (doRelu) { v0 = fmaxf(v0, 0.f); v1 = fmaxf(v1, 0.f); }
                    outP[((size_t)img * (Cout >> 1) + (oc >> 1)) * HW + row * WW + colb2 + 16 * p]
                        = pack_h2(v0, v1);
                }
            }
        }
    } else {
#pragma unroll
        for (int co = 0; co < 16; co++) {
            const int oc = cob + co;
            if (oc < Cout) {
                const float b = bias[oc];
#pragma unroll
                for (int p = 0; p < 4; p++) {
                    float v = acc[p][co] + b;
                    if (doRelu) v = fmaxf(v, 0.f);
                    outF[((size_t)img * Cout + oc) * HW + row * WW + colb2 + 16 * p] = v;
                }
            }
        }
    }
}

// ---------------- host launcher ----------------
static inline void launch_conv_ffma(const void* in, const float* w, const float* b,
                                    void* out, int Cin, int Cout, int relu,
                                    int inPair, int outPair)
{
    dim3 grid(16, NIMG, (Cout + 15) / 16);
    conv3x3_kernel<<<grid, 256>>>(in, w, b, out, Cin, Cout, relu, inPair, outPair);
}

static inline void launch_conv_tc(const unsigned* in, const unsigned* wp, const float* b,
                                  unsigned* out, const unsigned* add,
                                  int Cin, int Cout, int flags)
{
    dim3 grid(HH, NIMG, (Cout + 63) / 64);
    conv3x3_tc2<<<grid, 256>>>(in, wp, b, out, add, Cin, Cout, flags);
}

extern "C" void kernel_launch(void* const* d_in, const int* in_sizes, int n_in,
                              void* d_out, int out_size)
{
    const float* x       = (const float*)d_in[0];
    const float* w_init  = (const float*)d_in[1];
    const float* b_init  = (const float*)d_in[2];
    const float* res_w1  = (const float*)d_in[3];
    const float* res_b1  = (const float*)d_in[4];
    const float* res_w2  = (const float*)d_in[5];
    const float* res_b2  = (const float*)d_in[6];
    const float* w_bn    = (const float*)d_in[7];
    const float* b_bn    = (const float*)d_in[8];
    const float* off_w   = (const float*)d_in[9];
    const float* off_b   = (const float*)d_in[10];
    const float* com_w   = (const float*)d_in[11];
    const float* com_b   = (const float*)d_in[12];
    const float* dcn_w   = (const float*)d_in[13];
    const float* dcn_b   = (const float*)d_in[14];
    const float* w_rec   = (const float*)d_in[15];
    const float* b_rec   = (const float*)d_in[16];
    float* out = (float*)d_out;

    unsigned *bufA, *bufB, *bufT, *obuf, *om, *wprep;
    cudaGetSymbolAddress((void**)&bufA, g_bufA);
    cudaGetSymbolAddress((void**)&bufB, g_bufB);
    cudaGetSymbolAddress((void**)&bufT, g_bufT);
    cudaGetSymbolAddress((void**)&obuf, g_off);
    cudaGetSymbolAddress((void**)&om,   g_om);
    cudaGetSymbolAddress((void**)&wprep, g_wprep);

    // ---- single fused weight prep ----
    prep_all_kernel<<<2592, 256>>>(res_w1, res_w2, w_bn, off_w, com_w, dcn_w, wprep);
    const unsigned* pw_r1[5]; const unsigned* pw_r2[5];
    for (int i = 0; i < 5; i++) { pw_r1[i] = wprep + (size_t)i * 18432; pw_r2[i] = wprep + (size_t)(5 + i) * 18432; }
    const unsigned* pw_bn = wprep + 184320;
    const unsigned* pw_off[4]; const unsigned* pw_com[4]; const unsigned* pw_gemm[4];
    for (int d = 0; d < 4; d++) {
        pw_off[d]  = wprep + 221184 + (size_t)d * 18432;
        pw_com[d]  = wprep + 294912 + (size_t)d * 73728;
        pw_gemm[d] = wprep + 589824 + (size_t)d * 18432;
    }

    // ---- network ----
    // 1) init conv + relu (Cin=1, FFMA): fp32 in -> pair-fp16 out
    launch_conv_ffma(x, w_init, b_init, bufA, 1, 64, 1, 0, 1);

    // 2) 5 residual blocks (fp16 MMA, pair layout)
    unsigned* cur = bufA;
    unsigned* nxt = bufB;
    for (int i = 0; i < 5; i++) {
        launch_conv_tc(cur, pw_r1[i], res_b1 + i * 64, bufT, nullptr, 64, 64, 1);
        launch_conv_tc(bufT, pw_r2[i], res_b2 + i * 64, nxt, cur, 64, 64, 0);
        unsigned* t = cur; cur = nxt; nxt = t;
    }
    unsigned* feat = cur;

    // 3) bottleneck conv over [ref | nei] (cat folded into loads)
    launch_conv_tc(feat, pw_bn, b_bn, bufA, nullptr, 128, 64, 4);

    // 4) four chained DCN stages
    dim3 ggemm(HW / 128, NIMG);
    auto dcn_stage = [&](const unsigned* xsrc, const unsigned* feaSrc, int di, unsigned* outBuf) {
        launch_conv_tc(feaSrc, pw_off[di], off_b + di * 64, obuf, nullptr, 64, 64, 0);
        launch_conv_tc(obuf, pw_com[di], com_b + di * 216, om, nullptr, 64, 216, 0);
        dcn_fused_kernel<<<ggemm, 256>>>(pw_gemm[di], xsrc, om, dcn_b + di * 64, outBuf);
    };

    dcn_stage(bufA, bufA, 0, bufT);   // fea = dcn(fea, o0)
    dcn_stage(bufT, bufT, 1, bufA);   // fea = dcn(fea, o1)
    dcn_stage(feat, bufA, 2, bufT);   // fea = dcn(nei, o2)
    dcn_stage(bufT, bufT, 3, bufA);   // aligned = dcn(fea, o3)

    // 5) reconstruction conv (Cout=1, FFMA): pair-fp16 in -> fp32 out
    launch_conv_ffma(bufA, w_rec, b_rec, out, 64, 1, 0, 1, 0);
}